// round 15
// baseline (speedup 1.0000x reference)
#include <cuda_runtime.h>
#include <cstdint>

// ResRNN, int16-quantized recurrent weights, f32x2 dequant-FMA, cross-barrier
// weight prefetch, row-pairing + 2-way K-split (R10 structure). R15 = R14
// (296 CTAs x 512 threads, 2 co-resident CTAs/SM via __launch_bounds__(512,2))
// with the copy_hfinal launch fixed to cover all HD elements (R14's only bug:
// output 0 passed, output 1 was half-poisoned by a 1024-thread copy).

#define T_    512
#define IND   1024
#define HD    2048
#define H2    4096
#define OUTD  1024
#define NCTA  296
#define NTHR  512

typedef unsigned long long ull;

__device__ float g_XI[T_ * HD];
__device__ float g_A1[T_ * H2];
__device__ float g_Hs[T_ * HD];
__device__ float g_z [H2];
__device__ float g_y2[H2];
__device__ unsigned g_bar  = 0;
__device__ unsigned g_done = 0;

__device__ unsigned short g_qL1h[(size_t)H2 * HD];
__device__ unsigned short g_qL2 [(size_t)H2 * H2];
__device__ unsigned short g_qXh [(size_t)HD * H2];
__device__ float g_sL1h[H2];
__device__ float g_sL2 [H2];
__device__ float g_sXh [HD];

// ---------------------------------------------------------------------------
// fp32 GEMM:  C[M,N] = A[M,K] * B[N,K]^T + bias[N]   (64x64x16 tiles —
// measured-fastest variant)
// ---------------------------------------------------------------------------
__global__ void __launch_bounds__(256) gemm_tt(
    const float* __restrict__ A, int lda,
    const float* __restrict__ B, int ldb,
    const float* __restrict__ bias,
    float* __restrict__ C, int ldc,
    int K)
{
    __shared__ float As[16][65];
    __shared__ float Bs[16][65];
    const int tx = threadIdx.x & 15;
    const int ty = threadIdx.x >> 4;
    const int m0 = blockIdx.y * 64;
    const int n0 = blockIdx.x * 64;

    float acc[4][4] = {};

    for (int k0 = 0; k0 < K; k0 += 16) {
#pragma unroll
        for (int i = threadIdx.x; i < 1024; i += 256) {
            int r  = i >> 4;
            int kk = i & 15;
            As[kk][r] = A[(size_t)(m0 + r) * lda + k0 + kk];
            Bs[kk][r] = B[(size_t)(n0 + r) * ldb + k0 + kk];
        }
        __syncthreads();
#pragma unroll
        for (int kk = 0; kk < 16; kk++) {
            float a[4], b[4];
#pragma unroll
            for (int i = 0; i < 4; i++) a[i] = As[kk][ty * 4 + i];
#pragma unroll
            for (int j = 0; j < 4; j++) b[j] = Bs[kk][tx * 4 + j];
#pragma unroll
            for (int i = 0; i < 4; i++)
#pragma unroll
                for (int j = 0; j < 4; j++)
                    acc[i][j] = fmaf(a[i], b[j], acc[i][j]);
        }
        __syncthreads();
    }

#pragma unroll
    for (int i = 0; i < 4; i++) {
        int m = m0 + ty * 4 + i;
#pragma unroll
        for (int j = 0; j < 4; j++) {
            int n = n0 + tx * 4 + j;
            C[(size_t)m * ldc + n] = acc[i][j] + bias[n];
        }
    }
}

// ---------------------------------------------------------------------------
// Merged per-row int16 quantization for all three recurrent matrices.
// ---------------------------------------------------------------------------
__global__ void __launch_bounds__(256) quantize_all(
    const float* __restrict__ l1_w,
    const float* __restrict__ l2_w,
    const float* __restrict__ xh2h_w)
{
    const int b = blockIdx.x;
    const float* src; int r, ld, col0, ncols;
    unsigned short* dst; float* scales;
    if (b < H2) {
        r = b;          src = l1_w;   ld = H2; col0 = HD; ncols = HD;
        dst = g_qL1h;   scales = g_sL1h;
    } else if (b < 2 * H2) {
        r = b - H2;     src = l2_w;   ld = H2; col0 = 0;  ncols = H2;
        dst = g_qL2;    scales = g_sL2;
    } else {
        r = b - 2 * H2; src = xh2h_w; ld = H2; col0 = 0;  ncols = H2;
        dst = g_qXh;    scales = g_sXh;
    }

    const float* row = src + (size_t)r * ld + col0;
    __shared__ float red[256];

    float m = 0.f;
    for (int i = threadIdx.x; i < ncols; i += 256)
        m = fmaxf(m, fabsf(row[i]));
    red[threadIdx.x] = m;
    __syncthreads();
    for (int s = 128; s; s >>= 1) {
        if (threadIdx.x < s)
            red[threadIdx.x] = fmaxf(red[threadIdx.x], red[threadIdx.x + s]);
        __syncthreads();
    }
    const float mx  = red[0];
    const float inv = (mx > 0.f) ? 32767.0f / mx : 0.f;
    if (threadIdx.x == 0)
        scales[r] = (mx > 0.f) ? mx / 32767.0f : 1.0f;

    unsigned short* drow = dst + (size_t)r * ncols;
    for (int i = threadIdx.x; i < ncols; i += 256) {
        int q = __float2int_rn(row[i] * inv);
        drow[i] = (unsigned short)(q + 32768);
    }
}

// ---------------------------------------------------------------------------
// f32x2 helpers
// ---------------------------------------------------------------------------
__device__ __forceinline__ ull pack2(unsigned lo, unsigned hi) {
    ull r;
    asm("mov.b64 %0, {%1, %2};" : "=l"(r) : "r"(lo), "r"(hi));
    return r;
}
__device__ __forceinline__ ull add2(ull a, ull b) {
    ull r;
    asm("add.rn.f32x2 %0, %1, %2;" : "=l"(r) : "l"(a), "l"(b));
    return r;
}
__device__ __forceinline__ ull fma2(ull a, ull b, ull c) {
    ull r;
    asm("fma.rn.f32x2 %0, %1, %2, %3;" : "=l"(r) : "l"(a), "l"(b), "l"(c));
    return r;
}

__device__ __forceinline__ float warp_red(float v) {
#pragma unroll
    for (int o = 16; o; o >>= 1) v += __shfl_down_sync(0xffffffffu, v, o);
    return v;
}

// -8421376.0f (= -(2^23 + 2^15)) in both lanes
#define NMAG2 0xCB008000CB008000ull

// dequant 2 biased-u16 (packed in u32) -> f32x2
__device__ __forceinline__ ull dq(unsigned u) {
    return add2(pack2(__byte_perm(u, 0x4B000000u, 0x7410),
                      __byte_perm(u, 0x4B000000u, 0x7432)), NMAG2);
}

// process one 16B weight group for TWO rows, sharing the x loads.
__device__ __forceinline__ void proc8p(uint4 w0, uint4 w1, int i,
                                       const ulonglong2* __restrict__ x2,
                                       ull& a00, ull& a01,
                                       ull& a10, ull& a11)
{
    int sw = (i >> 2) & 7;
    ulonglong2 X0 = x2[(2 * i) ^ sw];
    ulonglong2 X1 = x2[(2 * i) ^ sw ^ 1];
    a00 = fma2(dq(w0.x), X0.x, a00);
    a01 = fma2(dq(w0.y), X0.y, a01);
    a10 = fma2(dq(w1.x), X0.x, a10);
    a11 = fma2(dq(w1.y), X0.y, a11);
    a00 = fma2(dq(w0.z), X1.x, a00);
    a01 = fma2(dq(w0.w), X1.y, a01);
    a10 = fma2(dq(w1.z), X1.x, a10);
    a11 = fma2(dq(w1.w), X1.y, a11);
}

// half-K paired dequant-dot: rows q0,q1, NIT iterations starting at uint4
// index ioff. First group arrives prefetched.
template <int NIT>
__device__ __forceinline__ float2 dotq_ph(
    const uint4* __restrict__ q0, const uint4* __restrict__ q1,
    const float4* __restrict__ xs, int lane, int ioff,
    uint4 pf0, uint4 pf1)
{
    const ulonglong2* x2 = reinterpret_cast<const ulonglong2*>(xs);
    ull a00 = 0, a01 = 0, a10 = 0, a11 = 0;
    proc8p(pf0, pf1, ioff + lane, x2, a00, a01, a10, a11);
#pragma unroll
    for (int k = 1; k < NIT; k++) {
        int i = ioff + lane + 32 * k;
        uint4 w0 = __ldcg(q0 + i);
        uint4 w1 = __ldcg(q1 + i);
        proc8p(w0, w1, i, x2, a00, a01, a10, a11);
    }
    a00 = add2(a00, a01);
    a10 = add2(a10, a11);
    unsigned lo, hi;
    float2 s;
    asm("mov.b64 {%0, %1}, %2;" : "=r"(lo), "=r"(hi) : "l"(a00));
    s.x = warp_red(__uint_as_float(lo) + __uint_as_float(hi));
    asm("mov.b64 {%0, %1}, %2;" : "=r"(lo), "=r"(hi) : "l"(a10));
    s.y = warp_red(__uint_as_float(lo) + __uint_as_float(hi));
    return s;
}

// R2/R10 barrier (best measured), target scaled to 296 CTAs.
#define GRID_SYNC() do {                                                      \
    __syncthreads();                                                          \
    if (tid == 0) {                                                           \
        __threadfence();                                                      \
        atomicAdd(&g_bar, 1u);                                                \
        ep++;                                                                 \
        unsigned tgt = ep * (unsigned)NCTA;                                   \
        unsigned v;                                                           \
        while (1) {                                                           \
            asm volatile("ld.global.acquire.gpu.u32 %0, [%1];"                \
                         : "=r"(v) : "l"(&g_bar));                            \
            if (v >= tgt) break;                                              \
            __nanosleep(32);                                                  \
        }                                                                     \
    }                                                                         \
    __syncthreads();                                                          \
} while (0)

__global__ void __launch_bounds__(NTHR, 2) resrnn_seq(
    const float* __restrict__ h0,
    const float* __restrict__ l2b,
    const float* __restrict__ xh2hb)
{
    __shared__ float4 hs4[HD / 4];    //  8 KB: h_prev, swizzled
    __shared__ float4 sb4[H2 / 4];    // 16 KB: phase input vector, swizzled
    __shared__ float2 spart[16];      // per-warp partial sums
    const int tid  = threadIdx.x;
    const int wid  = tid >> 5;
    const int lane = tid & 31;
    const int bid  = blockIdx.x;
    const int half = wid & 1;                   // which K-half this warp does
    const int p    = bid + NCTA * (wid >> 1);   // row-pair index
    unsigned  ep   = 0;

    const bool vAB = (p < H2 / 2);
    const bool vC  = (p < HD / 2);
    const int pAB = vAB ? p : 0;
    const int pC  = vC  ? p : 0;
    const uint4* qA0 = reinterpret_cast<const uint4*>(
        g_qL1h + (size_t)(2 * pAB) * HD);
    const uint4* qA1 = reinterpret_cast<const uint4*>(
        g_qL1h + (size_t)(2 * pAB + 1) * HD);
    const uint4* qB0 = reinterpret_cast<const uint4*>(
        g_qL2 + (size_t)(2 * pAB) * H2);
    const uint4* qB1 = reinterpret_cast<const uint4*>(
        g_qL2 + (size_t)(2 * pAB + 1) * H2);
    const uint4* qC0 = reinterpret_cast<const uint4*>(
        g_qXh + (size_t)(2 * pC) * H2);
    const uint4* qC1 = reinterpret_cast<const uint4*>(
        g_qXh + (size_t)(2 * pC + 1) * H2);

    const int ioffA  = half * (HD / 16);   // 128 uint4 per half (phase A)
    const int ioffBC = half * (H2 / 16);   // 256 uint4 per half (phases B/C)

    // initial prefetch: phase A of step 0
    uint4 pf0 = make_uint4(0, 0, 0, 0), pf1 = pf0;
    if (vAB) {
        pf0 = __ldcg(qA0 + ioffA + lane);
        pf1 = __ldcg(qA1 + ioffA + lane);
    }

    for (int t = 0; t < T_; t++) {
        const float4* hprev4 = (t == 0)
            ? reinterpret_cast<const float4*>(h0)
            : reinterpret_cast<const float4*>(&g_Hs[(size_t)(t - 1) * HD]);

        // ---- stage h_prev (swizzled) ----
        for (int j = tid; j < HD / 4; j += NTHR)
            hs4[j ^ ((j >> 3) & 7)] = __ldcg(hprev4 + j);
        __syncthreads();

        // ---- Phase A: z = relu(A1[t] + l1h @ h) ----
        if (vAB) {
            float2 s = dotq_ph<4>(qA0, qA1, hs4, lane, ioffA, pf0, pf1);
            if (lane == 0) spart[wid] = s;
        }
        if (vAB) {
            pf0 = __ldcg(qB0 + ioffBC + lane);
            pf1 = __ldcg(qB1 + ioffBC + lane);
        }
        __syncthreads();
        if (vAB && half == 0 && lane == 0) {
            float2 sa = spart[wid], sb = spart[wid + 1];
            float2 a1 = __ldcg(reinterpret_cast<const float2*>(
                &g_A1[(size_t)t * H2 + 2 * p]));
            const float2 sc = *reinterpret_cast<const float2*>(&g_sL1h[2 * p]);
            float2 z;
            z.x = fmaxf(a1.x + sc.x * (sa.x + sb.x), 0.f);
            z.y = fmaxf(a1.y + sc.y * (sa.y + sb.y), 0.f);
            *reinterpret_cast<float2*>(&g_z[2 * p]) = z;
        }
        GRID_SYNC();

        // ---- Phase B: y2 = l2 @ z + l2_b ----
        {
            const float4* z4 = reinterpret_cast<const float4*>(g_z);
            for (int j = tid; j < H2 / 4; j += NTHR)
                sb4[j ^ ((j >> 3) & 7)] = __ldcg(z4 + j);
        }
        __syncthreads();
        if (vAB) {
            float2 s = dotq_ph<8>(qB0, qB1, sb4, lane, ioffBC, pf0, pf1);
            if (lane == 0) spart[wid] = s;
        }
        if (vC) {
            pf0 = __ldcg(qC0 + ioffBC + lane);
            pf1 = __ldcg(qC1 + ioffBC + lane);
        }
        __syncthreads();
        if (vAB && half == 0 && lane == 0) {
            float2 sa = spart[wid], sb = spart[wid + 1];
            const float2 sc = *reinterpret_cast<const float2*>(&g_sL2[2 * p]);
            float2 b = __ldcg(reinterpret_cast<const float2*>(l2b + 2 * p));
            float2 y;
            y.x = sc.x * (sa.x + sb.x) + b.x;
            y.y = sc.y * (sa.y + sb.y) + b.y;
            *reinterpret_cast<float2*>(&g_y2[2 * p]) = y;
        }
        GRID_SYNC();

        // ---- Phase C: temp = relu(xh + y2); h' = xh2h @ temp + b ----
        {
            const float4* xi4 = reinterpret_cast<const float4*>(
                &g_XI[(size_t)t * HD]);
            const float4* y4 = reinterpret_cast<const float4*>(g_y2);
            for (int j = tid; j < H2 / 4; j += NTHR) {
                float4 xh;
                if (j < HD / 4) {
                    xh = __ldcg(xi4 + j);
                } else {
                    int jj = j - HD / 4;
                    xh = hs4[jj ^ ((jj >> 3) & 7)];   // unswizzle h
                }
                float4 y = __ldcg(y4 + j);
                float4 tv;
                tv.x = fmaxf(xh.x + y.x, 0.f);
                tv.y = fmaxf(xh.y + y.y, 0.f);
                tv.z = fmaxf(xh.z + y.z, 0.f);
                tv.w = fmaxf(xh.w + y.w, 0.f);
                sb4[j ^ ((j >> 3) & 7)] = tv;
            }
        }
        __syncthreads();
        if (vC) {
            float2 s = dotq_ph<8>(qC0, qC1, sb4, lane, ioffBC, pf0, pf1);
            if (lane == 0) spart[wid] = s;
        }
        if (vAB) {
            pf0 = __ldcg(qA0 + ioffA + lane);
            pf1 = __ldcg(qA1 + ioffA + lane);
        }
        __syncthreads();
        if (vC && half == 0 && lane == 0) {
            float2 sa = spart[wid], sb = spart[wid + 1];
            const float2 sc = *reinterpret_cast<const float2*>(&g_sXh[2 * p]);
            float2 b = __ldcg(reinterpret_cast<const float2*>(xh2hb + 2 * p));
            float2 h;
            h.x = sc.x * (sa.x + sb.x) + b.x;
            h.y = sc.y * (sa.y + sb.y) + b.y;
            *reinterpret_cast<float2*>(&g_Hs[(size_t)t * HD + 2 * p]) = h;
        }
        GRID_SYNC();
    }

    // Reset barrier for next graph replay (handshake: nobody still spinning).
    if (tid == 0) {
        __threadfence();
        atomicAdd(&g_done, 1u);
        if (bid == 0) {
            unsigned v;
            while (1) {
                asm volatile("ld.global.acquire.gpu.u32 %0, [%1];"
                             : "=r"(v) : "l"(&g_done));
                if (v >= (unsigned)NCTA) break;
                __nanosleep(64);
            }
            g_bar  = 0u;
            g_done = 0u;
            __threadfence();
        }
    }
}

__global__ void copy_hfinal(float* __restrict__ out)
{
    int i = blockIdx.x * blockDim.x + threadIdx.x;
    if (i < HD) out[i] = g_Hs[(size_t)(T_ - 1) * HD + i];
}

// ---------------------------------------------------------------------------
extern "C" void kernel_launch(void* const* d_in, const int* in_sizes, int n_in,
                              void* d_out, int out_size)
{
    const float* x      = (const float*)d_in[0];
    const float* h0     = (const float*)d_in[1];
    const float* inp_w  = (const float*)d_in[2];
    const float* inp_b  = (const float*)d_in[3];
    const float* l1_w   = (const float*)d_in[4];
    const float* l1_b   = (const float*)d_in[5];
    const float* l2_w   = (const float*)d_in[6];
    const float* l2_b   = (const float*)d_in[7];
    const float* xh2h_w = (const float*)d_in[8];
    const float* xh2h_b = (const float*)d_in[9];
    const float* out_w  = (const float*)d_in[10];
    const float* out_b  = (const float*)d_in[11];

    float *pXI, *pA1, *pHs;
    cudaGetSymbolAddress((void**)&pXI, g_XI);
    cudaGetSymbolAddress((void**)&pA1, g_A1);
    cudaGetSymbolAddress((void**)&pHs, g_Hs);

    // K1: XI[512,2048] = x * inp_w^T + inp_b
    gemm_tt<<<dim3(HD / 64, T_ / 64), 256>>>(x, IND, inp_w, IND, inp_b,
                                             pXI, HD, IND);
    // K2: A1[512,4096] = XI * l1_w[:, :2048]^T + l1_b
    gemm_tt<<<dim3(H2 / 64, T_ / 64), 256>>>(pXI, HD, l1_w, H2, l1_b,
                                             pA1, H2, HD);
    // Quantize all recurrent weights in one launch
    quantize_all<<<2 * H2 + HD, 256>>>(l1_w, l2_w, xh2h_w);

    // Sequential recurrence (4th launch -> ncu -s 5 captures it)
    resrnn_seq<<<NCTA, NTHR>>>(h0, l2_b, xh2h_b);

    // K3: ys[512,1024] = Hs * out_w^T + out_b
    gemm_tt<<<dim3(OUTD / 64, T_ / 64), 256>>>(pHs, HD, out_w, HD, out_b,
                                               (float*)d_out, OUTD, HD);

    // h_final: 4 blocks x 512 threads = 2048 threads covers HD exactly
    // (R14 bug: 2 x 512 = 1024 left half of h_final poisoned)
    if (out_size >= T_ * OUTD + HD) {
        copy_hfinal<<<4, NTHR>>>((float*)d_out + (size_t)T_ * OUTD);
    }
}

// round 16
// speedup vs baseline: 1.1481x; 1.1481x over previous
#include <cuda_runtime.h>
#include <cstdint>

// ResRNN, int16-quantized recurrent weights, f32x2 dequant-FMA, cross-barrier
// weight prefetch, row-pairing + 2-way K-split. Seq kernel is BIT-IDENTICAL
// to R10 (best measured, 6368us). R16 single change: gemm_tt rewritten with
// float4 LDS + double-buffered K pipeline (same 64x64x16 tile shape).

#define T_    512
#define IND   1024
#define HD    2048
#define H2    4096
#define OUTD  1024
#define NCTA  148
#define NTHR  1024

typedef unsigned long long ull;

__device__ float g_XI[T_ * HD];
__device__ float g_A1[T_ * H2];
__device__ float g_Hs[T_ * HD];
__device__ float g_z [H2];
__device__ float g_y2[H2];
__device__ unsigned g_bar  = 0;
__device__ unsigned g_done = 0;

__device__ unsigned short g_qL1h[(size_t)H2 * HD];
__device__ unsigned short g_qL2 [(size_t)H2 * H2];
__device__ unsigned short g_qXh [(size_t)HD * H2];
__device__ float g_sL1h[H2];
__device__ float g_sL2 [H2];
__device__ float g_sXh [HD];

// ---------------------------------------------------------------------------
// fp32 GEMM:  C[M,N] = A[M,K] * B[N,K]^T + bias[N]
// 64x64x16 tiles, 256 threads, 4x4/thread. float4 LDS + double-buffered K.
// M,N % 64 == 0, K % 16 == 0 (true for all calls).
// ---------------------------------------------------------------------------
__global__ void __launch_bounds__(256) gemm_tt(
    const float* __restrict__ A, int lda,
    const float* __restrict__ B, int ldb,
    const float* __restrict__ bias,
    float* __restrict__ C, int ldc,
    int K)
{
    // row length 68 floats = 272B (16B-aligned rows, 17 float4 per row)
    __shared__ __align__(16) float As[2][16][68];
    __shared__ __align__(16) float Bs[2][16][68];
    const int tid = threadIdx.x;
    const int tx = tid & 15;
    const int ty = tid >> 4;
    const int m0 = blockIdx.y * 64;
    const int n0 = blockIdx.x * 64;

    // staging role: thread i loads row r = i>>2, k-quad q = i&3 of each tile
    const int sr = tid >> 2;
    const int sq = tid & 3;
    const float4* Ag = reinterpret_cast<const float4*>(
        A + (size_t)(m0 + sr) * lda) + sq;
    const float4* Bg = reinterpret_cast<const float4*>(
        B + (size_t)(n0 + sr) * ldb) + sq;
    const int kstep4 = 4;   // 16 floats = 4 float4 per K-tile

    float acc[4][4] = {};

    // prologue: stage tile 0 into buffer 0
    {
        float4 va = __ldg(Ag);
        float4 vb = __ldg(Bg);
        As[0][sq * 4 + 0][sr] = va.x;
        As[0][sq * 4 + 1][sr] = va.y;
        As[0][sq * 4 + 2][sr] = va.z;
        As[0][sq * 4 + 3][sr] = va.w;
        Bs[0][sq * 4 + 0][sr] = vb.x;
        Bs[0][sq * 4 + 1][sr] = vb.y;
        Bs[0][sq * 4 + 2][sr] = vb.z;
        Bs[0][sq * 4 + 3][sr] = vb.w;
    }
    __syncthreads();

    const int ntile = K >> 4;
    for (int kt = 0; kt < ntile; kt++) {
        const int buf = kt & 1;
        float4 va, vb;
        const bool more = (kt + 1 < ntile);
        if (more) {
            va = __ldg(Ag + (kt + 1) * kstep4);
            vb = __ldg(Bg + (kt + 1) * kstep4);
        }

#pragma unroll
        for (int kk = 0; kk < 16; kk++) {
            float4 a4 = *reinterpret_cast<const float4*>(&As[buf][kk][ty * 4]);
            float4 b4 = *reinterpret_cast<const float4*>(&Bs[buf][kk][tx * 4]);
            float a[4] = {a4.x, a4.y, a4.z, a4.w};
            float b[4] = {b4.x, b4.y, b4.z, b4.w};
#pragma unroll
            for (int i = 0; i < 4; i++)
#pragma unroll
                for (int j = 0; j < 4; j++)
                    acc[i][j] = fmaf(a[i], b[j], acc[i][j]);
        }

        if (more) {
            const int nb = buf ^ 1;
            As[nb][sq * 4 + 0][sr] = va.x;
            As[nb][sq * 4 + 1][sr] = va.y;
            As[nb][sq * 4 + 2][sr] = va.z;
            As[nb][sq * 4 + 3][sr] = va.w;
            Bs[nb][sq * 4 + 0][sr] = vb.x;
            Bs[nb][sq * 4 + 1][sr] = vb.y;
            Bs[nb][sq * 4 + 2][sr] = vb.z;
            Bs[nb][sq * 4 + 3][sr] = vb.w;
            __syncthreads();
        }
    }

#pragma unroll
    for (int i = 0; i < 4; i++) {
        int m = m0 + ty * 4 + i;
#pragma unroll
        for (int j = 0; j < 4; j++) {
            int n = n0 + tx * 4 + j;
            C[(size_t)m * ldc + n] = acc[i][j] + bias[n];
        }
    }
}

// ---------------------------------------------------------------------------
// Merged per-row int16 quantization for all three recurrent matrices.
// ---------------------------------------------------------------------------
__global__ void __launch_bounds__(256) quantize_all(
    const float* __restrict__ l1_w,
    const float* __restrict__ l2_w,
    const float* __restrict__ xh2h_w)
{
    const int b = blockIdx.x;
    const float* src; int r, ld, col0, ncols;
    unsigned short* dst; float* scales;
    if (b < H2) {
        r = b;          src = l1_w;   ld = H2; col0 = HD; ncols = HD;
        dst = g_qL1h;   scales = g_sL1h;
    } else if (b < 2 * H2) {
        r = b - H2;     src = l2_w;   ld = H2; col0 = 0;  ncols = H2;
        dst = g_qL2;    scales = g_sL2;
    } else {
        r = b - 2 * H2; src = xh2h_w; ld = H2; col0 = 0;  ncols = H2;
        dst = g_qXh;    scales = g_sXh;
    }

    const float* row = src + (size_t)r * ld + col0;
    __shared__ float red[256];

    float m = 0.f;
    for (int i = threadIdx.x; i < ncols; i += 256)
        m = fmaxf(m, fabsf(row[i]));
    red[threadIdx.x] = m;
    __syncthreads();
    for (int s = 128; s; s >>= 1) {
        if (threadIdx.x < s)
            red[threadIdx.x] = fmaxf(red[threadIdx.x], red[threadIdx.x + s]);
        __syncthreads();
    }
    const float mx  = red[0];
    const float inv = (mx > 0.f) ? 32767.0f / mx : 0.f;
    if (threadIdx.x == 0)
        scales[r] = (mx > 0.f) ? mx / 32767.0f : 1.0f;

    unsigned short* drow = dst + (size_t)r * ncols;
    for (int i = threadIdx.x; i < ncols; i += 256) {
        int q = __float2int_rn(row[i] * inv);
        drow[i] = (unsigned short)(q + 32768);
    }
}

// ---------------------------------------------------------------------------
// f32x2 helpers
// ---------------------------------------------------------------------------
__device__ __forceinline__ ull pack2(unsigned lo, unsigned hi) {
    ull r;
    asm("mov.b64 %0, {%1, %2};" : "=l"(r) : "r"(lo), "r"(hi));
    return r;
}
__device__ __forceinline__ ull add2(ull a, ull b) {
    ull r;
    asm("add.rn.f32x2 %0, %1, %2;" : "=l"(r) : "l"(a), "l"(b));
    return r;
}
__device__ __forceinline__ ull fma2(ull a, ull b, ull c) {
    ull r;
    asm("fma.rn.f32x2 %0, %1, %2, %3;" : "=l"(r) : "l"(a), "l"(b), "l"(c));
    return r;
}

__device__ __forceinline__ float warp_red(float v) {
#pragma unroll
    for (int o = 16; o; o >>= 1) v += __shfl_down_sync(0xffffffffu, v, o);
    return v;
}

// -8421376.0f (= -(2^23 + 2^15)) in both lanes
#define NMAG2 0xCB008000CB008000ull

// dequant 2 biased-u16 (packed in u32) -> f32x2
__device__ __forceinline__ ull dq(unsigned u) {
    return add2(pack2(__byte_perm(u, 0x4B000000u, 0x7410),
                      __byte_perm(u, 0x4B000000u, 0x7432)), NMAG2);
}

// process one 16B weight group for TWO rows, sharing the x loads.
__device__ __forceinline__ void proc8p(uint4 w0, uint4 w1, int i,
                                       const ulonglong2* __restrict__ x2,
                                       ull& a00, ull& a01,
                                       ull& a10, ull& a11)
{
    int sw = (i >> 2) & 7;
    ulonglong2 X0 = x2[(2 * i) ^ sw];
    ulonglong2 X1 = x2[(2 * i) ^ sw ^ 1];
    a00 = fma2(dq(w0.x), X0.x, a00);
    a01 = fma2(dq(w0.y), X0.y, a01);
    a10 = fma2(dq(w1.x), X0.x, a10);
    a11 = fma2(dq(w1.y), X0.y, a11);
    a00 = fma2(dq(w0.z), X1.x, a00);
    a01 = fma2(dq(w0.w), X1.y, a01);
    a10 = fma2(dq(w1.z), X1.x, a10);
    a11 = fma2(dq(w1.w), X1.y, a11);
}

// half-K paired dequant-dot: rows q0,q1, NIT iterations starting at uint4
// index ioff. First group arrives prefetched.
template <int NIT>
__device__ __forceinline__ float2 dotq_ph(
    const uint4* __restrict__ q0, const uint4* __restrict__ q1,
    const float4* __restrict__ xs, int lane, int ioff,
    uint4 pf0, uint4 pf1)
{
    const ulonglong2* x2 = reinterpret_cast<const ulonglong2*>(xs);
    ull a00 = 0, a01 = 0, a10 = 0, a11 = 0;
    proc8p(pf0, pf1, ioff + lane, x2, a00, a01, a10, a11);
#pragma unroll
    for (int k = 1; k < NIT; k++) {
        int i = ioff + lane + 32 * k;
        uint4 w0 = __ldcg(q0 + i);
        uint4 w1 = __ldcg(q1 + i);
        proc8p(w0, w1, i, x2, a00, a01, a10, a11);
    }
    a00 = add2(a00, a01);
    a10 = add2(a10, a11);
    unsigned lo, hi;
    float2 s;
    asm("mov.b64 {%0, %1}, %2;" : "=r"(lo), "=r"(hi) : "l"(a00));
    s.x = warp_red(__uint_as_float(lo) + __uint_as_float(hi));
    asm("mov.b64 {%0, %1}, %2;" : "=r"(lo), "=r"(hi) : "l"(a10));
    s.y = warp_red(__uint_as_float(lo) + __uint_as_float(hi));
    return s;
}

// R2/R10 barrier (best measured).
#define GRID_SYNC() do {                                                      \
    __syncthreads();                                                          \
    if (tid == 0) {                                                           \
        __threadfence();                                                      \
        atomicAdd(&g_bar, 1u);                                                \
        ep++;                                                                 \
        unsigned tgt = ep * (unsigned)NCTA;                                   \
        unsigned v;                                                           \
        while (1) {                                                           \
            asm volatile("ld.global.acquire.gpu.u32 %0, [%1];"                \
                         : "=r"(v) : "l"(&g_bar));                            \
            if (v >= tgt) break;                                              \
            __nanosleep(32);                                                  \
        }                                                                     \
    }                                                                         \
    __syncthreads();                                                          \
} while (0)

__global__ void __launch_bounds__(NTHR, 1) resrnn_seq(
    const float* __restrict__ h0,
    const float* __restrict__ l2b,
    const float* __restrict__ xh2hb)
{
    __shared__ float4 hs4[HD / 4];    //  8 KB: h_prev, swizzled
    __shared__ float4 sb4[H2 / 4];    // 16 KB: phase input vector, swizzled
    __shared__ float2 spart[32];      // per-warp partial sums
    const int tid  = threadIdx.x;
    const int wid  = tid >> 5;
    const int lane = tid & 31;
    const int bid  = blockIdx.x;
    const int half = wid & 1;                   // which K-half this warp does
    const int p    = bid + NCTA * (wid >> 1);   // row-pair index
    unsigned  ep   = 0;

    const bool vAB = (p < H2 / 2);
    const bool vC  = (p < HD / 2);
    const int pAB = vAB ? p : 0;
    const int pC  = vC  ? p : 0;
    const uint4* qA0 = reinterpret_cast<const uint4*>(
        g_qL1h + (size_t)(2 * pAB) * HD);
    const uint4* qA1 = reinterpret_cast<const uint4*>(
        g_qL1h + (size_t)(2 * pAB + 1) * HD);
    const uint4* qB0 = reinterpret_cast<const uint4*>(
        g_qL2 + (size_t)(2 * pAB) * H2);
    const uint4* qB1 = reinterpret_cast<const uint4*>(
        g_qL2 + (size_t)(2 * pAB + 1) * H2);
    const uint4* qC0 = reinterpret_cast<const uint4*>(
        g_qXh + (size_t)(2 * pC) * H2);
    const uint4* qC1 = reinterpret_cast<const uint4*>(
        g_qXh + (size_t)(2 * pC + 1) * H2);

    const int ioffA  = half * (HD / 16);   // 128 uint4 per half (phase A)
    const int ioffBC = half * (H2 / 16);   // 256 uint4 per half (phases B/C)

    // initial prefetch: phase A of step 0
    uint4 pf0 = make_uint4(0, 0, 0, 0), pf1 = pf0;
    if (vAB) {
        pf0 = __ldcg(qA0 + ioffA + lane);
        pf1 = __ldcg(qA1 + ioffA + lane);
    }

    for (int t = 0; t < T_; t++) {
        const float4* hprev4 = (t == 0)
            ? reinterpret_cast<const float4*>(h0)
            : reinterpret_cast<const float4*>(&g_Hs[(size_t)(t - 1) * HD]);

        // ---- stage h_prev (swizzled) ----
        for (int j = tid; j < HD / 4; j += NTHR)
            hs4[j ^ ((j >> 3) & 7)] = __ldcg(hprev4 + j);
        __syncthreads();

        // ---- Phase A: z = relu(A1[t] + l1h @ h) ----
        if (vAB) {
            float2 s = dotq_ph<4>(qA0, qA1, hs4, lane, ioffA, pf0, pf1);
            if (lane == 0) spart[wid] = s;
        }
        if (vAB) {
            pf0 = __ldcg(qB0 + ioffBC + lane);
            pf1 = __ldcg(qB1 + ioffBC + lane);
        }
        __syncthreads();
        if (vAB && half == 0 && lane == 0) {
            float2 sa = spart[wid], sb = spart[wid + 1];
            float2 a1 = __ldcg(reinterpret_cast<const float2*>(
                &g_A1[(size_t)t * H2 + 2 * p]));
            const float2 sc = *reinterpret_cast<const float2*>(&g_sL1h[2 * p]);
            float2 z;
            z.x = fmaxf(a1.x + sc.x * (sa.x + sb.x), 0.f);
            z.y = fmaxf(a1.y + sc.y * (sa.y + sb.y), 0.f);
            *reinterpret_cast<float2*>(&g_z[2 * p]) = z;
        }
        GRID_SYNC();

        // ---- Phase B: y2 = l2 @ z + l2_b ----
        {
            const float4* z4 = reinterpret_cast<const float4*>(g_z);
            for (int j = tid; j < H2 / 4; j += NTHR)
                sb4[j ^ ((j >> 3) & 7)] = __ldcg(z4 + j);
        }
        __syncthreads();
        if (vAB) {
            float2 s = dotq_ph<8>(qB0, qB1, sb4, lane, ioffBC, pf0, pf1);
            if (lane == 0) spart[wid] = s;
        }
        if (vC) {
            pf0 = __ldcg(qC0 + ioffBC + lane);
            pf1 = __ldcg(qC1 + ioffBC + lane);
        }
        __syncthreads();
        if (vAB && half == 0 && lane == 0) {
            float2 sa = spart[wid], sb = spart[wid + 1];
            const float2 sc = *reinterpret_cast<const float2*>(&g_sL2[2 * p]);
            float2 b = __ldcg(reinterpret_cast<const float2*>(l2b + 2 * p));
            float2 y;
            y.x = sc.x * (sa.x + sb.x) + b.x;
            y.y = sc.y * (sa.y + sb.y) + b.y;
            *reinterpret_cast<float2*>(&g_y2[2 * p]) = y;
        }
        GRID_SYNC();

        // ---- Phase C: temp = relu(xh + y2); h' = xh2h @ temp + b ----
        {
            const float4* xi4 = reinterpret_cast<const float4*>(
                &g_XI[(size_t)t * HD]);
            const float4* y4 = reinterpret_cast<const float4*>(g_y2);
            for (int j = tid; j < H2 / 4; j += NTHR) {
                float4 xh;
                if (j < HD / 4) {
                    xh = __ldcg(xi4 + j);
                } else {
                    int jj = j - HD / 4;
                    xh = hs4[jj ^ ((jj >> 3) & 7)];   // unswizzle h
                }
                float4 y = __ldcg(y4 + j);
                float4 tv;
                tv.x = fmaxf(xh.x + y.x, 0.f);
                tv.y = fmaxf(xh.y + y.y, 0.f);
                tv.z = fmaxf(xh.z + y.z, 0.f);
                tv.w = fmaxf(xh.w + y.w, 0.f);
                sb4[j ^ ((j >> 3) & 7)] = tv;
            }
        }
        __syncthreads();
        if (vC) {
            float2 s = dotq_ph<8>(qC0, qC1, sb4, lane, ioffBC, pf0, pf1);
            if (lane == 0) spart[wid] = s;
        }
        if (vAB) {
            pf0 = __ldcg(qA0 + ioffA + lane);
            pf1 = __ldcg(qA1 + ioffA + lane);
        }
        __syncthreads();
        if (vC && half == 0 && lane == 0) {
            float2 sa = spart[wid], sb = spart[wid + 1];
            const float2 sc = *reinterpret_cast<const float2*>(&g_sXh[2 * p]);
            float2 b = __ldcg(reinterpret_cast<const float2*>(xh2hb + 2 * p));
            float2 h;
            h.x = sc.x * (sa.x + sb.x) + b.x;
            h.y = sc.y * (sa.y + sb.y) + b.y;
            *reinterpret_cast<float2*>(&g_Hs[(size_t)t * HD + 2 * p]) = h;
        }
        GRID_SYNC();
    }

    // Reset barrier for next graph replay (handshake: nobody still spinning).
    if (tid == 0) {
        __threadfence();
        atomicAdd(&g_done, 1u);
        if (bid == 0) {
            unsigned v;
            while (1) {
                asm volatile("ld.global.acquire.gpu.u32 %0, [%1];"
                             : "=r"(v) : "l"(&g_done));
                if (v >= (unsigned)NCTA) break;
                __nanosleep(64);
            }
            g_bar  = 0u;
            g_done = 0u;
            __threadfence();
        }
    }
}

__global__ void copy_hfinal(float* __restrict__ out)
{
    int i = blockIdx.x * blockDim.x + threadIdx.x;
    if (i < HD) out[i] = g_Hs[(size_t)(T_ - 1) * HD + i];
}

// ---------------------------------------------------------------------------
extern "C" void kernel_launch(void* const* d_in, const int* in_sizes, int n_in,
                              void* d_out, int out_size)
{
    const float* x      = (const float*)d_in[0];
    const float* h0     = (const float*)d_in[1];
    const float* inp_w  = (const float*)d_in[2];
    const float* inp_b  = (const float*)d_in[3];
    const float* l1_w   = (const float*)d_in[4];
    const float* l1_b   = (const float*)d_in[5];
    const float* l2_w   = (const float*)d_in[6];
    const float* l2_b   = (const float*)d_in[7];
    const float* xh2h_w = (const float*)d_in[8];
    const float* xh2h_b = (const float*)d_in[9];
    const float* out_w  = (const float*)d_in[10];
    const float* out_b  = (const float*)d_in[11];

    float *pXI, *pA1, *pHs;
    cudaGetSymbolAddress((void**)&pXI, g_XI);
    cudaGetSymbolAddress((void**)&pA1, g_A1);
    cudaGetSymbolAddress((void**)&pHs, g_Hs);

    // K1: XI[512,2048] = x * inp_w^T + inp_b
    gemm_tt<<<dim3(HD / 64, T_ / 64), 256>>>(x, IND, inp_w, IND, inp_b,
                                             pXI, HD, IND);
    // K2: A1[512,4096] = XI * l1_w[:, :2048]^T + l1_b
    gemm_tt<<<dim3(H2 / 64, T_ / 64), 256>>>(pXI, HD, l1_w, H2, l1_b,
                                             pA1, H2, HD);
    // Quantize all recurrent weights in one launch
    quantize_all<<<2 * H2 + HD, 256>>>(l1_w, l2_w, xh2h_w);

    // Sequential recurrence (4th launch -> ncu -s 5 captures it)
    resrnn_seq<<<NCTA, NTHR>>>(h0, l2_b, xh2h_b);

    // K3: ys[512,1024] = Hs * out_w^T + out_b
    gemm_tt<<<dim3(OUTD / 64, T_ / 64), 256>>>(pHs, HD, out_w, HD, out_b,
                                               (float*)d_out, OUTD, HD);

    if (out_size >= T_ * OUTD + HD) {
        copy_hfinal<<<2, NTHR>>>((float*)d_out + (size_t)T_ * OUTD);
    }
}